// round 4
// baseline (speedup 1.0000x reference)
#include <cuda_runtime.h>
#include <cstdint>

#define B_ 16
#define S_ 4096
#define DQ_ 1024
#define DM_ 512
#define DO_ 1024
#define H_ 16
#define D_ 64

typedef unsigned long long u64;

// -------- scratch (no allocs allowed) --------
__device__ float g_q[B_ * DO_];          // scaled query projections [b][h*64+d]
__device__ float g_ut[B_ * DM_ * H_];    // folded key proj, TRANSPOSED: [b][m][h]
__device__ float g_c[B_ * H_ * DM_];     // attn-weighted mb sums [b][h][m]

// -------- packed fp32x2 helpers (Blackwell FFMA2) --------
__device__ __forceinline__ u64 pack2(float lo, float hi) {
    u64 r; asm("mov.b64 %0, {%1,%2};" : "=l"(r) : "f"(lo), "f"(hi)); return r;
}
__device__ __forceinline__ void unpack2(u64 v, float& lo, float& hi) {
    asm("mov.b64 {%0,%1}, %2;" : "=f"(lo), "=f"(hi) : "l"(v));
}
__device__ __forceinline__ void ffma2(u64& d, u64 a, u64 b) {
    asm("fma.rn.f32x2 %0, %1, %2, %3;" : "=l"(d) : "l"(a), "l"(b), "l"(d));
}

// ============================================================
// Kernel 0: zero the g_c accumulator (replaces cudaMemsetAsync to
// keep kernel_launch to pure kernel launches during graph capture)
// ============================================================
__global__ __launch_bounds__(256) void k_zero_c() {
    int i = blockIdx.x * 256 + threadIdx.x;
    if (i < B_ * H_ * DM_) g_c[i] = 0.f;
}

// ============================================================
// Kernel 1: q[b, h*64+d] = (source[b,:] @ Wq[:, o]) * 1/sqrt(64)
// grid (DO/256, B), block 256
// ============================================================
__global__ __launch_bounds__(256) void k_qproj(const float* __restrict__ src,
                                               const float* __restrict__ Wq) {
    __shared__ float s_src[DQ_];
    int b = blockIdx.y;
    for (int i = threadIdx.x; i < DQ_; i += 256) s_src[i] = src[b * DQ_ + i];
    __syncthreads();
    int o = blockIdx.x * 256 + threadIdx.x;
    float acc = 0.f;
#pragma unroll 8
    for (int i = 0; i < DQ_; ++i)
        acc = fmaf(s_src[i], Wq[(size_t)i * DO_ + o], acc);
    g_q[b * DO_ + o] = acc * 0.125f;
}

// ============================================================
// Kernel 2: u[b,h,m] = sum_d Wk[m, h*64+d] * q[b,h,d]
// stored transposed: g_ut[(b*DM + m)*H + h]
// grid B*H, block 256
// ============================================================
__global__ __launch_bounds__(256) void k_uproj(const float* __restrict__ Wk) {
    int bh = blockIdx.x;
    int b = bh >> 4, h = bh & 15;
    __shared__ float s_q[D_];
    if (threadIdx.x < D_) s_q[threadIdx.x] = g_q[b * DO_ + h * D_ + threadIdx.x];
    __syncthreads();
    for (int m = threadIdx.x; m < DM_; m += 256) {
        const float4* w = reinterpret_cast<const float4*>(Wk + (size_t)m * DO_ + h * D_);
        float acc = 0.f;
#pragma unroll
        for (int d4 = 0; d4 < D_ / 4; ++d4) {
            float4 wv = w[d4];
            acc = fmaf(wv.x, s_q[d4 * 4 + 0], acc);
            acc = fmaf(wv.y, s_q[d4 * 4 + 1], acc);
            acc = fmaf(wv.z, s_q[d4 * 4 + 2], acc);
            acc = fmaf(wv.w, s_q[d4 * 4 + 3], acc);
        }
        g_ut[((size_t)b * DM_ + m) * H_ + h] = acc;
    }
}

// ============================================================
// Kernel 3: raw scores[b,h,s] = sum_m mb[b,s,m] * u[b,h,m]
// grid (S/256, B), block 256
// ============================================================
#define TS3 256
#define KC3 32
__global__ __launch_bounds__(256) void k_scores(const float* __restrict__ mb,
                                                float* __restrict__ attn) {
    __shared__ float mb_s[TS3][KC3 + 1];              // [s][m], pitch 33 (conflict-free)
    __shared__ __align__(16) float u_s[KC3][H_];      // [m][h]
    int b = blockIdx.y;
    int s_tile = blockIdx.x * TS3;
    int t = threadIdx.x, w = t >> 5, l = t & 31;
    int s_loc = w * 32 + (l & 7) * 4;                 // 4 consecutive s
    int h0 = (l >> 3) * 4;                            // 4 consecutive h (2 pairs)

    u64 acc[2][4];
#pragma unroll
    for (int i = 0; i < 2; ++i)
#pragma unroll
        for (int j = 0; j < 4; ++j) acc[i][j] = 0ull;

    const float* mb_b = mb + ((size_t)b * S_ + s_tile) * DM_;
    const float* u_b = g_ut + (size_t)b * DM_ * H_;

    for (int kc = 0; kc < DM_ / KC3; ++kc) {
        __syncthreads();
        // stage mb tile: 256 rows x 32 floats
#pragma unroll
        for (int i = 0; i < 8; ++i) {
            int idx = i * 256 + t;
            int row = idx >> 3, f4 = idx & 7;
            float4 v = *reinterpret_cast<const float4*>(
                mb_b + (size_t)row * DM_ + kc * KC3 + f4 * 4);
            mb_s[row][f4 * 4 + 0] = v.x;
            mb_s[row][f4 * 4 + 1] = v.y;
            mb_s[row][f4 * 4 + 2] = v.z;
            mb_s[row][f4 * 4 + 3] = v.w;
        }
        // stage u tile: 32 m x 16 h
#pragma unroll
        for (int i = 0; i < 2; ++i) {
            int idx = i * 256 + t;
            int m = idx >> 4, h = idx & 15;
            u_s[m][h] = u_b[(size_t)(kc * KC3 + m) * H_ + h];
        }
        __syncthreads();
#pragma unroll
        for (int k = 0; k < KC3; ++k) {
            ulonglong2 up = *reinterpret_cast<const ulonglong2*>(&u_s[k][h0]);
            float m0 = mb_s[s_loc + 0][k];
            float m1 = mb_s[s_loc + 1][k];
            float m2 = mb_s[s_loc + 2][k];
            float m3 = mb_s[s_loc + 3][k];
            u64 d0 = pack2(m0, m0), d1 = pack2(m1, m1);
            u64 d2 = pack2(m2, m2), d3 = pack2(m3, m3);
            ffma2(acc[0][0], up.x, d0); ffma2(acc[1][0], up.y, d0);
            ffma2(acc[0][1], up.x, d1); ffma2(acc[1][1], up.y, d1);
            ffma2(acc[0][2], up.x, d2); ffma2(acc[1][2], up.y, d2);
            ffma2(acc[0][3], up.x, d3); ffma2(acc[1][3], up.y, d3);
        }
    }
#pragma unroll
    for (int hp = 0; hp < 2; ++hp) {
        float v0l, v0h, v1l, v1h, v2l, v2h, v3l, v3h;
        unpack2(acc[hp][0], v0l, v0h);
        unpack2(acc[hp][1], v1l, v1h);
        unpack2(acc[hp][2], v2l, v2h);
        unpack2(acc[hp][3], v3l, v3h);
        int h_lo = h0 + hp * 2;
        float4 lo4 = {v0l, v1l, v2l, v3l};
        float4 hi4 = {v0h, v1h, v2h, v3h};
        *reinterpret_cast<float4*>(attn + (size_t)(b * H_ + h_lo) * S_ + s_tile + s_loc) = lo4;
        *reinterpret_cast<float4*>(attn + (size_t)(b * H_ + h_lo + 1) * S_ + s_tile + s_loc) = hi4;
    }
}

// ============================================================
// Kernel 4: masked softmax over each (b,h) row of 4096, in place.
// mask is INT32 (harness canonicalizes bool -> int32). True = masked out.
// grid B*H, block 256 (16 elements/thread)
// ============================================================
__global__ __launch_bounds__(256) void k_softmax(float* __restrict__ attn,
                                                 const int* __restrict__ mask) {
    __shared__ float red[256];
    int bh = blockIdx.x;
    int b = bh >> 4;
    float* row = attn + (size_t)bh * S_;
    const int* mrow = mask + (size_t)b * S_;
    float v[16];
    float mx = -3.0e38f;
#pragma unroll
    for (int i = 0; i < 16; ++i) {
        int s = threadIdx.x + i * 256;
        float x = row[s];
        if (mrow[s] != 0) x = -1.0e18f;
        v[i] = x;
        mx = fmaxf(mx, x);
    }
    red[threadIdx.x] = mx;
    __syncthreads();
    for (int off = 128; off > 0; off >>= 1) {
        if (threadIdx.x < off) red[threadIdx.x] = fmaxf(red[threadIdx.x], red[threadIdx.x + off]);
        __syncthreads();
    }
    float MX = red[0];
    __syncthreads();
    float sum = 0.f;
#pragma unroll
    for (int i = 0; i < 16; ++i) {
        v[i] = expf(v[i] - MX);
        sum += v[i];
    }
    red[threadIdx.x] = sum;
    __syncthreads();
    for (int off = 128; off > 0; off >>= 1) {
        if (threadIdx.x < off) red[threadIdx.x] += red[threadIdx.x + off];
        __syncthreads();
    }
    float inv = 1.f / red[0];
#pragma unroll
    for (int i = 0; i < 16; ++i) row[threadIdx.x + i * 256] = v[i] * inv;
}

// ============================================================
// Kernel 5: c[b,h,m] += sum_s attn[b,h,s] * mb[b,s,m]
// grid (2, 16, B), block 256
// ============================================================
#define SC5 32
#define MT5 256
__global__ __launch_bounds__(256) void k_ctxacc(const float* __restrict__ mb,
                                                const float* __restrict__ attn) {
    __shared__ __align__(16) float mb_s[SC5][MT5 + 4];  // [s][m], pitch 260
    __shared__ float a_s[SC5][H_ + 1];                  // [s][h], pitch 17
    int mt = blockIdx.x;
    int sc = blockIdx.y;
    int b = blockIdx.z;
    int m_base = mt * MT5;
    int s_base = sc * 256;
    int t = threadIdx.x, w = t >> 5, l = t & 31;
    int m_loc = w * 32 + (l & 7) * 4;
    int h0 = (l >> 3) * 4;

    u64 acc[4][2];  // [h][mpair]
#pragma unroll
    for (int i = 0; i < 4; ++i)
#pragma unroll
        for (int j = 0; j < 2; ++j) acc[i][j] = 0ull;

    const float* mb_b = mb + ((size_t)b * S_ + s_base) * DM_ + m_base;
    const float* a_b = attn + (size_t)b * H_ * S_ + s_base;

    for (int ch = 0; ch < 8; ++ch) {
        __syncthreads();
#pragma unroll
        for (int i = 0; i < 8; ++i) {
            int idx = i * 256 + t;
            int row = idx >> 6, f4 = idx & 63;
            float4 v = *reinterpret_cast<const float4*>(
                mb_b + (size_t)(ch * 32 + row) * DM_ + f4 * 4);
            *reinterpret_cast<float4*>(&mb_s[row][f4 * 4]) = v;
        }
#pragma unroll
        for (int i = 0; i < 2; ++i) {
            int idx = i * 256 + t;
            int h = idx >> 5, s_l = idx & 31;
            a_s[s_l][h] = a_b[(size_t)h * S_ + ch * 32 + s_l];
        }
        __syncthreads();
#pragma unroll
        for (int k = 0; k < SC5; ++k) {
            ulonglong2 mp = *reinterpret_cast<const ulonglong2*>(&mb_s[k][m_loc]);
            float a0 = a_s[k][h0 + 0];
            float a1 = a_s[k][h0 + 1];
            float a2 = a_s[k][h0 + 2];
            float a3 = a_s[k][h0 + 3];
            u64 d0 = pack2(a0, a0), d1 = pack2(a1, a1);
            u64 d2 = pack2(a2, a2), d3 = pack2(a3, a3);
            ffma2(acc[0][0], mp.x, d0); ffma2(acc[0][1], mp.y, d0);
            ffma2(acc[1][0], mp.x, d1); ffma2(acc[1][1], mp.y, d1);
            ffma2(acc[2][0], mp.x, d2); ffma2(acc[2][1], mp.y, d2);
            ffma2(acc[3][0], mp.x, d3); ffma2(acc[3][1], mp.y, d3);
        }
    }
#pragma unroll
    for (int j = 0; j < 4; ++j) {
        float x0, x1, x2, x3;
        unpack2(acc[j][0], x0, x1);
        unpack2(acc[j][1], x2, x3);
        float* dst = g_c + (size_t)(b * H_ + h0 + j) * DM_ + m_base + m_loc;
        atomicAdd(dst + 0, x0);
        atomicAdd(dst + 1, x1);
        atomicAdd(dst + 2, x2);
        atomicAdd(dst + 3, x3);
    }
}

// ============================================================
// Kernel 6: context[b, h*64+d] = sum_m c[b,h,m] * Wv[m, h*64+d]
// grid B*H, block 64
// ============================================================
__global__ __launch_bounds__(64) void k_ctx(const float* __restrict__ Wv,
                                            float* __restrict__ out) {
    int bh = blockIdx.x;
    int b = bh >> 4, h = bh & 15;
    __shared__ float s_c[DM_];
    for (int i = threadIdx.x; i < DM_; i += 64) s_c[i] = g_c[(size_t)bh * DM_ + i];
    __syncthreads();
    int d = threadIdx.x;
    float acc = 0.f;
#pragma unroll 8
    for (int m = 0; m < DM_; ++m)
        acc = fmaf(s_c[m], Wv[(size_t)m * DO_ + h * D_ + d], acc);
    out[(size_t)b * DO_ + h * D_ + d] = acc;
}

// ============================================================
extern "C" void kernel_launch(void* const* d_in, const int* in_sizes, int n_in,
                              void* d_out, int out_size) {
    const float* src = (const float*)d_in[0];
    const float* mb = (const float*)d_in[1];
    const float* Wq = (const float*)d_in[2];
    const float* Wk = (const float*)d_in[3];
    const float* Wv = (const float*)d_in[4];
    const int* mask = (const int*)d_in[5];
    float* out = (float*)d_out;
    float* attn = out + B_ * DO_;  // context first, then attn [B,H,S]

    k_zero_c<<<(B_ * H_ * DM_ + 255) / 256, 256>>>();
    k_qproj<<<dim3(DO_ / 256, B_), 256>>>(src, Wq);
    k_uproj<<<B_ * H_, 256>>>(Wk);
    k_scores<<<dim3(S_ / TS3, B_), 256>>>(mb, attn);
    k_softmax<<<B_ * H_, 256>>>(attn, mask);
    k_ctxacc<<<dim3(2, 16, B_), 256>>>(mb, attn);
    k_ctx<<<B_ * H_, 64>>>(Wv, out);
}

// round 6
// speedup vs baseline: 1.7220x; 1.7220x over previous
#include <cuda_runtime.h>
#include <cstdint>

#define B_ 16
#define S_ 4096
#define DQ_ 1024
#define DM_ 512
#define DO_ 1024
#define H_ 16
#define D_ 64

typedef unsigned long long u64;

// -------- scratch (no allocs allowed) --------
__device__ float g_q[B_ * DO_];          // scaled query projections [b][h*64+d]
__device__ float g_ut[B_ * DM_ * H_];    // folded key proj, TRANSPOSED: [b][m][h]
__device__ float g_c[B_ * H_ * DM_];     // attn-weighted mb sums [b][h][m]

// -------- packed fp32x2 helpers --------
__device__ __forceinline__ u64 pack2(float lo, float hi) {
    u64 r; asm("mov.b64 %0, {%1,%2};" : "=l"(r) : "f"(lo), "f"(hi)); return r;
}
__device__ __forceinline__ void unpack2(u64 v, float& lo, float& hi) {
    asm("mov.b64 {%0,%1}, %2;" : "=f"(lo), "=f"(hi) : "l"(v));
}
__device__ __forceinline__ void ffma2(u64& d, u64 a, u64 b) {
    asm("fma.rn.f32x2 %0, %1, %2, %3;" : "=l"(d) : "l"(a), "l"(b), "l"(d));
}

// ============================================================
// Kernel 0: zero accumulators (g_q, g_c, context slice of out)
// grid 512, block 256
// ============================================================
__global__ __launch_bounds__(256) void k_zero(float* __restrict__ out) {
    int i = blockIdx.x * 256 + threadIdx.x;
    if (i < B_ * DO_) { g_q[i] = 0.f; out[i] = 0.f; }
    if (i < B_ * H_ * DM_) g_c[i] = 0.f;
}

// ============================================================
// Kernel 1: q partial: for k-slice, all b at once (Wq read ONCE).
// q[b,o] += sum_{k in slice} src[b,k] * Wq[k,o]; scaled by 0.125.
// grid (DO/256=4, DQ/64=16), block 256
// ============================================================
__global__ __launch_bounds__(256) void k_qproj(const float* __restrict__ src,
                                               const float* __restrict__ Wq) {
    __shared__ float s_src[B_][64];
    int t = threadIdx.x;
    int o = blockIdx.x * 256 + t;
    int k0 = blockIdx.y * 64;
#pragma unroll
    for (int i = 0; i < 4; ++i) {
        int idx = i * 256 + t;
        s_src[idx >> 6][idx & 63] = src[(size_t)(idx >> 6) * DQ_ + k0 + (idx & 63)];
    }
    __syncthreads();
    float acc[B_];
#pragma unroll
    for (int b = 0; b < B_; ++b) acc[b] = 0.f;
#pragma unroll 4
    for (int k = 0; k < 64; ++k) {
        float wq = Wq[(size_t)(k0 + k) * DO_ + o];
#pragma unroll
        for (int b = 0; b < B_; ++b) acc[b] = fmaf(s_src[b][k], wq, acc[b]);
    }
#pragma unroll
    for (int b = 0; b < B_; ++b) atomicAdd(&g_q[b * DO_ + o], acc[b] * 0.125f);
}

// ============================================================
// Kernel 2: u[b,h,m] = sum_d Wk[m, h*64+d] * q[b,h,d]
// stored transposed: g_ut[(b*DM + m)*H + h]
// grid B*H, block 256
// ============================================================
__global__ __launch_bounds__(256) void k_uproj(const float* __restrict__ Wk) {
    int bh = blockIdx.x;
    int b = bh >> 4, h = bh & 15;
    __shared__ float s_q[D_];
    if (threadIdx.x < D_) s_q[threadIdx.x] = g_q[b * DO_ + h * D_ + threadIdx.x];
    __syncthreads();
    for (int m = threadIdx.x; m < DM_; m += 256) {
        const float4* w = reinterpret_cast<const float4*>(Wk + (size_t)m * DO_ + h * D_);
        float acc = 0.f;
#pragma unroll
        for (int d4 = 0; d4 < D_ / 4; ++d4) {
            float4 wv = w[d4];
            acc = fmaf(wv.x, s_q[d4 * 4 + 0], acc);
            acc = fmaf(wv.y, s_q[d4 * 4 + 1], acc);
            acc = fmaf(wv.z, s_q[d4 * 4 + 2], acc);
            acc = fmaf(wv.w, s_q[d4 * 4 + 3], acc);
        }
        g_ut[((size_t)b * DM_ + m) * H_ + h] = acc;
    }
}

// ============================================================
// Kernel 3: raw scores[b,h,s] = sum_m mb[b,s,m] * u[b,h,m]
// TS=128, block 128 -> grid 512 CTAs, ~6 CTAs/SM for latency hiding
// ============================================================
#define TS3 128
#define KC3 32
__global__ __launch_bounds__(128) void k_scores(const float* __restrict__ mb,
                                                float* __restrict__ attn) {
    __shared__ float mb_s[TS3][KC3 + 1];              // pitch 33, conflict-free
    __shared__ __align__(16) float u_s[KC3][H_];
    int b = blockIdx.y;
    int s_tile = blockIdx.x * TS3;
    int t = threadIdx.x, w = t >> 5, l = t & 31;
    int s_loc = w * 32 + (l & 7) * 4;                 // 4 consecutive s
    int h0 = (l >> 3) * 4;                            // 4 consecutive h

    u64 acc[2][4];
#pragma unroll
    for (int i = 0; i < 2; ++i)
#pragma unroll
        for (int j = 0; j < 4; ++j) acc[i][j] = 0ull;

    const float* mb_b = mb + ((size_t)b * S_ + s_tile) * DM_;
    const float* u_b = g_ut + (size_t)b * DM_ * H_;

    for (int kc = 0; kc < DM_ / KC3; ++kc) {
        __syncthreads();
#pragma unroll
        for (int i = 0; i < 8; ++i) {
            int idx = i * 128 + t;
            int row = idx >> 3, f4 = idx & 7;
            float4 v = *reinterpret_cast<const float4*>(
                mb_b + (size_t)row * DM_ + kc * KC3 + f4 * 4);
            mb_s[row][f4 * 4 + 0] = v.x;
            mb_s[row][f4 * 4 + 1] = v.y;
            mb_s[row][f4 * 4 + 2] = v.z;
            mb_s[row][f4 * 4 + 3] = v.w;
        }
#pragma unroll
        for (int i = 0; i < 4; ++i) {
            int idx = i * 128 + t;
            int m = idx >> 4, h = idx & 15;
            u_s[m][h] = u_b[(size_t)(kc * KC3 + m) * H_ + h];
        }
        __syncthreads();
#pragma unroll
        for (int k = 0; k < KC3; ++k) {
            ulonglong2 up = *reinterpret_cast<const ulonglong2*>(&u_s[k][h0]);
            float m0 = mb_s[s_loc + 0][k];
            float m1 = mb_s[s_loc + 1][k];
            float m2 = mb_s[s_loc + 2][k];
            float m3 = mb_s[s_loc + 3][k];
            u64 d0 = pack2(m0, m0), d1 = pack2(m1, m1);
            u64 d2 = pack2(m2, m2), d3 = pack2(m3, m3);
            ffma2(acc[0][0], up.x, d0); ffma2(acc[1][0], up.y, d0);
            ffma2(acc[0][1], up.x, d1); ffma2(acc[1][1], up.y, d1);
            ffma2(acc[0][2], up.x, d2); ffma2(acc[1][2], up.y, d2);
            ffma2(acc[0][3], up.x, d3); ffma2(acc[1][3], up.y, d3);
        }
    }
#pragma unroll
    for (int hp = 0; hp < 2; ++hp) {
        float v0l, v0h, v1l, v1h, v2l, v2h, v3l, v3h;
        unpack2(acc[hp][0], v0l, v0h);
        unpack2(acc[hp][1], v1l, v1h);
        unpack2(acc[hp][2], v2l, v2h);
        unpack2(acc[hp][3], v3l, v3h);
        int h_lo = h0 + hp * 2;
        float4 lo4 = {v0l, v1l, v2l, v3l};
        float4 hi4 = {v0h, v1h, v2h, v3h};
        *reinterpret_cast<float4*>(attn + (size_t)(b * H_ + h_lo) * S_ + s_tile + s_loc) = lo4;
        *reinterpret_cast<float4*>(attn + (size_t)(b * H_ + h_lo + 1) * S_ + s_tile + s_loc) = hi4;
    }
}

// ============================================================
// Kernel 4: masked softmax per (b,h) row, in place. mask is int32.
// grid B*H, block 256
// ============================================================
__global__ __launch_bounds__(256) void k_softmax(float* __restrict__ attn,
                                                 const int* __restrict__ mask) {
    __shared__ float red[256];
    int bh = blockIdx.x;
    int b = bh >> 4;
    float* row = attn + (size_t)bh * S_;
    const int* mrow = mask + (size_t)b * S_;
    float v[16];
    float mx = -3.0e38f;
#pragma unroll
    for (int i = 0; i < 16; ++i) {
        int s = threadIdx.x + i * 256;
        float x = row[s];
        if (mrow[s] != 0) x = -1.0e18f;
        v[i] = x;
        mx = fmaxf(mx, x);
    }
    red[threadIdx.x] = mx;
    __syncthreads();
    for (int off = 128; off > 0; off >>= 1) {
        if (threadIdx.x < off) red[threadIdx.x] = fmaxf(red[threadIdx.x], red[threadIdx.x + off]);
        __syncthreads();
    }
    float MX = red[0];
    __syncthreads();
    float sum = 0.f;
#pragma unroll
    for (int i = 0; i < 16; ++i) {
        v[i] = expf(v[i] - MX);
        sum += v[i];
    }
    red[threadIdx.x] = sum;
    __syncthreads();
    for (int off = 128; off > 0; off >>= 1) {
        if (threadIdx.x < off) red[threadIdx.x] += red[threadIdx.x + off];
        __syncthreads();
    }
    float inv = 1.f / red[0];
#pragma unroll
    for (int i = 0; i < 16; ++i) row[threadIdx.x + i * 256] = v[i] * inv;
}

// ============================================================
// Kernel 5: c[b,h,m] += sum_s attn[b,h,s] * mb[b,s,m]
// MT=128, block 128 -> grid (4,16,16)=1024 CTAs
// ============================================================
#define SC5 32
#define MT5 128
__global__ __launch_bounds__(128) void k_ctxacc(const float* __restrict__ mb,
                                                const float* __restrict__ attn) {
    __shared__ __align__(16) float mb_s[SC5][MT5 + 4];  // pitch 132
    __shared__ float a_s[SC5][H_ + 1];                  // pitch 17
    int m_base = blockIdx.x * MT5;
    int s_base = blockIdx.y * 256;
    int b = blockIdx.z;
    int t = threadIdx.x, w = t >> 5, l = t & 31;
    int m_loc = w * 32 + (l & 7) * 4;
    int h0 = (l >> 3) * 4;

    u64 acc[4][2];
#pragma unroll
    for (int i = 0; i < 4; ++i)
#pragma unroll
        for (int j = 0; j < 2; ++j) acc[i][j] = 0ull;

    const float* mb_b = mb + ((size_t)b * S_ + s_base) * DM_ + m_base;
    const float* a_b = attn + (size_t)b * H_ * S_ + s_base;

    for (int ch = 0; ch < 8; ++ch) {
        __syncthreads();
#pragma unroll
        for (int i = 0; i < 8; ++i) {
            int idx = i * 128 + t;
            int row = idx >> 5, f4 = idx & 31;
            float4 v = *reinterpret_cast<const float4*>(
                mb_b + (size_t)(ch * 32 + row) * DM_ + f4 * 4);
            *reinterpret_cast<float4*>(&mb_s[row][f4 * 4]) = v;
        }
#pragma unroll
        for (int i = 0; i < 4; ++i) {
            int idx = i * 128 + t;
            int h = idx >> 5, s_l = idx & 31;
            a_s[s_l][h] = a_b[(size_t)h * S_ + ch * 32 + s_l];
        }
        __syncthreads();
#pragma unroll
        for (int k = 0; k < SC5; ++k) {
            ulonglong2 mp = *reinterpret_cast<const ulonglong2*>(&mb_s[k][m_loc]);
            float a0 = a_s[k][h0 + 0];
            float a1 = a_s[k][h0 + 1];
            float a2 = a_s[k][h0 + 2];
            float a3 = a_s[k][h0 + 3];
            u64 d0 = pack2(a0, a0), d1 = pack2(a1, a1);
            u64 d2 = pack2(a2, a2), d3 = pack2(a3, a3);
            ffma2(acc[0][0], mp.x, d0); ffma2(acc[0][1], mp.y, d0);
            ffma2(acc[1][0], mp.x, d1); ffma2(acc[1][1], mp.y, d1);
            ffma2(acc[2][0], mp.x, d2); ffma2(acc[2][1], mp.y, d2);
            ffma2(acc[3][0], mp.x, d3); ffma2(acc[3][1], mp.y, d3);
        }
    }
#pragma unroll
    for (int j = 0; j < 4; ++j) {
        float x0, x1, x2, x3;
        unpack2(acc[j][0], x0, x1);
        unpack2(acc[j][1], x2, x3);
        float* dst = g_c + (size_t)(b * H_ + h0 + j) * DM_ + m_base + m_loc;
        atomicAdd(dst + 0, x0);
        atomicAdd(dst + 1, x1);
        atomicAdd(dst + 2, x2);
        atomicAdd(dst + 3, x3);
    }
}

// ============================================================
// Kernel 6: context[b, h*64+d] += sum_{m in slice} c[b,h,m]*Wv[m,h*64+d]
// Wv tile staged ONCE, reused by all 16 b. grid (H, DM/64=8), block 256
// ============================================================
__global__ __launch_bounds__(256) void k_ctx(const float* __restrict__ Wv,
                                             float* __restrict__ out) {
    __shared__ float wv_s[64][65];
    __shared__ float c_s[B_][64];
    int h = blockIdx.x;
    int m0 = blockIdx.y * 64;
    int t = threadIdx.x;
#pragma unroll
    for (int i = 0; i < 16; ++i) {
        int idx = i * 256 + t;
        wv_s[idx >> 6][idx & 63] = Wv[(size_t)(m0 + (idx >> 6)) * DO_ + h * D_ + (idx & 63)];
    }
#pragma unroll
    for (int i = 0; i < 4; ++i) {
        int idx = i * 256 + t;
        c_s[idx >> 6][idx & 63] = g_c[(size_t)((idx >> 6) * H_ + h) * DM_ + m0 + (idx & 63)];
    }
    __syncthreads();
    int d = t & 63, bg = t >> 6;
    float acc[4] = {0.f, 0.f, 0.f, 0.f};
#pragma unroll 8
    for (int mm = 0; mm < 64; ++mm) {
        float wv = wv_s[mm][d];
#pragma unroll
        for (int j = 0; j < 4; ++j) acc[j] = fmaf(c_s[bg + j * 4][mm], wv, acc[j]);
    }
#pragma unroll
    for (int j = 0; j < 4; ++j)
        atomicAdd(&out[(size_t)(bg + j * 4) * DO_ + h * D_ + d], acc[j]);
}

// ============================================================
extern "C" void kernel_launch(void* const* d_in, const int* in_sizes, int n_in,
                              void* d_out, int out_size) {
    const float* src = (const float*)d_in[0];
    const float* mb = (const float*)d_in[1];
    const float* Wq = (const float*)d_in[2];
    const float* Wk = (const float*)d_in[3];
    const float* Wv = (const float*)d_in[4];
    const int* mask = (const int*)d_in[5];
    float* out = (float*)d_out;
    float* attn = out + B_ * DO_;  // context first, then attn [B,H,S]

    k_zero<<<512, 256>>>(out);
    k_qproj<<<dim3(DO_ / 256, DQ_ / 64), 256>>>(src, Wq);
    k_uproj<<<B_ * H_, 256>>>(Wk);
    k_scores<<<dim3(S_ / TS3, B_), 128>>>(mb, attn);
    k_softmax<<<B_ * H_, 256>>>(attn, mask);
    k_ctxacc<<<dim3(DM_ / MT5, S_ / 256, B_), 128>>>(mb, attn);
    k_ctx<<<dim3(H_, DM_ / 64), 256>>>(Wv, out);
}